// round 4
// baseline (speedup 1.0000x reference)
#include <cuda_runtime.h>
#include <cuda_bf16.h>

// Problem constants (hardcoded from reference):
//   PROJ=128, H=128, G=2, D=96, T=33, NEG=-1e9

#define NEG_VAL (-1000000000.0f)

// Scratch (device globals -- no allocations allowed)
__device__ float g_E[2 * 33 * 96 * 128];   // node embeddings
__device__ float g_A[2 * 32 * 96 * 128];   // xne @ udW1[0:128]
__device__ float g_B[2 * 32 * 96 * 128];   // xce @ udW1[128:256]
__device__ float g_C[2 * 96 * 96 * 128];   // ee  @ udW1[256:288]

// ---- f32x2 packed-FMA helpers (Blackwell) ----------------------------------
__device__ __forceinline__ void ffma2(unsigned long long& d, unsigned long long a,
                                      unsigned long long b) {
    asm("fma.rn.f32x2 %0, %1, %2, %0;" : "+l"(d) : "l"(a), "l"(b));
}
__device__ __forceinline__ unsigned long long packdup(float x) {
    unsigned long long r;
    asm("mov.b64 %0, {%1, %1};" : "=l"(r) : "f"(x));
    return r;
}
__device__ __forceinline__ void unpack2(float& lo, float& hi, unsigned long long v) {
    asm("mov.b64 {%0, %1}, %2;" : "=f"(lo), "=f"(hi) : "l"(v));
}

// ---------------------------------------------------------------------------
// Kernel 1: node embeddings  E = relu(relu(x @ neW1 + b1) @ neW2 + b2)
// ---------------------------------------------------------------------------
#define EROWS 8
__global__ void k_node_embed(const float* __restrict__ x,
                             const float* __restrict__ W1, const float* __restrict__ b1,
                             const float* __restrict__ W2, const float* __restrict__ b2) {
    int r0 = blockIdx.x * EROWS;
    int tid = threadIdx.x;  // 128
    __shared__ float xv[EROWS][129];
    __shared__ float y1[EROWS][128];

    int g = r0 / (33 * 96);
    int rem = r0 % (33 * 96);
    int t = rem / 96;
    int i0 = rem % 96;
    const float* xb = x + (size_t)(g * 33 + t) * 128 * 192 + 96 * g + i0;

#pragma unroll
    for (int it = 0; it < 8; it++) {
        int e = tid + it * 128;
        int h = e >> 3;
        int ii = e & 7;
        xv[ii][h] = xb[h * 192 + ii];
    }
    __syncthreads();

    float acc[EROWS];
#pragma unroll
    for (int r = 0; r < EROWS; r++) acc[r] = b1[tid];
    for (int k = 0; k < 128; k++) {
        float w = W1[k * 128 + tid];
#pragma unroll
        for (int r = 0; r < EROWS; r++) acc[r] += xv[r][k] * w;
    }
#pragma unroll
    for (int r = 0; r < EROWS; r++) y1[r][tid] = fmaxf(acc[r], 0.0f);
    __syncthreads();

#pragma unroll
    for (int r = 0; r < EROWS; r++) acc[r] = b2[tid];
    for (int k = 0; k < 128; k++) {
        float w = W2[k * 128 + tid];
#pragma unroll
        for (int r = 0; r < EROWS; r++) acc[r] += y1[r][k] * w;
    }
#pragma unroll
    for (int r = 0; r < EROWS; r++) g_E[(r0 + r) * 128 + tid] = fmaxf(acc[r], 0.0f);
}

// ---------------------------------------------------------------------------
// Kernel 2: A/B projections + dist head.
// ---------------------------------------------------------------------------
#define PROWS 8
__global__ void k_proj_dist(const float* __restrict__ udW1,
                            const float* __restrict__ dpW1, const float* __restrict__ dpb1,
                            const float* __restrict__ dpW2, const float* __restrict__ dpb2,
                            const float* __restrict__ dpW3, const float* __restrict__ dpb3,
                            float* __restrict__ dist_out) {
    int r0 = blockIdx.x * PROWS;
    int tid = threadIdx.x;  // 128
    int g = r0 / (32 * 96);
    int rem = r0 % (32 * 96);
    int t = rem / 96;
    int i0 = rem % 96;

    __shared__ float Ec[PROWS][128];
    __shared__ float En[PROWS][128];
    __shared__ float y1d[PROWS][128];

    for (int e = tid; e < PROWS * 128; e += 128) {
        int r = e >> 7, k = e & 127;
        Ec[r][k] = g_E[((g * 33 + t) * 96 + i0 + r) * 128 + k];
        En[r][k] = g_E[((g * 33 + t + 1) * 96 + i0 + r) * 128 + k];
    }
    __syncthreads();

    float accA[PROWS], accB[PROWS], accD[PROWS];
#pragma unroll
    for (int r = 0; r < PROWS; r++) { accA[r] = 0.0f; accB[r] = 0.0f; accD[r] = 0.0f; }

    for (int k = 0; k < 128; k++) {
        float wa = udW1[k * 128 + tid];
        float wb = udW1[(128 + k) * 128 + tid];
        float wc = dpW1[k * 128 + tid];
        float wd = dpW1[(128 + k) * 128 + tid];
#pragma unroll
        for (int r = 0; r < PROWS; r++) {
            accA[r] += En[r][k] * wa;
            accB[r] += Ec[r][k] * wb;
            accD[r] += Ec[r][k] * wc + En[r][k] * wd;
        }
    }
    float db1 = dpb1[tid];
#pragma unroll
    for (int r = 0; r < PROWS; r++) {
        g_A[(r0 + r) * 128 + tid] = accA[r];
        g_B[(r0 + r) * 128 + tid] = accB[r];
        y1d[r][tid] = fmaxf(accD[r] + db1, 0.0f);
    }
    __syncthreads();

    int r = tid >> 4;
    int q = tid & 15;
    float s = 0.0f;
#pragma unroll
    for (int nn = 0; nn < 4; nn++) {
        int n = q * 4 + nn;
        float a = dpb2[n];
        for (int k = 0; k < 128; k++) a += y1d[r][k] * dpW2[k * 64 + n];
        s += fmaxf(a, 0.0f) * dpW3[n];
    }
#pragma unroll
    for (int off = 8; off; off >>= 1) s += __shfl_xor_sync(0xffffffffu, s, off);
    if (q == 0) dist_out[r0 + r] = s + dpb3[0];
}

// ---------------------------------------------------------------------------
// Kernel 3: edge MLP + C projection.
// ---------------------------------------------------------------------------
__global__ void k_ee_c(const float* __restrict__ edge_w,
                       const float* __restrict__ eeW1, const float* __restrict__ eeb1,
                       const float* __restrict__ eeW2, const float* __restrict__ eeb2,
                       const float* __restrict__ udW1) {
    int g = blockIdx.x / 96;
    int i = blockIdx.x % 96;
    int tid = threadIdx.x;  // 128

    __shared__ float l2s[96][33];
    __shared__ float w1s[32], b1s[32], b2s[32];
    __shared__ float w2s[32 * 32];
    __shared__ float w1cs[32 * 128];
    __shared__ float ews[96];

    if (tid < 32) { w1s[tid] = eeW1[tid]; b1s[tid] = eeb1[tid]; b2s[tid] = eeb2[tid]; }
    for (int e = tid; e < 1024; e += 128) w2s[e] = eeW2[e];
    for (int e = tid; e < 4096; e += 128) w1cs[e] = udW1[256 * 128 + e];
    if (tid < 96) ews[tid] = edge_w[(96 * g + i) * 192 + 96 * g + tid];
    __syncthreads();

    for (int e = tid; e < 96 * 32; e += 128) {
        int j = e >> 5, q = e & 31;
        float e0 = ews[j];
        float a = b2s[q];
#pragma unroll
        for (int p = 0; p < 32; p++) {
            float l1 = fmaxf(e0 * w1s[p] + b1s[p], 0.0f);
            a += l1 * w2s[p * 32 + q];
        }
        l2s[j][q] = fmaxf(a, 0.0f);
    }
    __syncthreads();

    float* Cout = g_C + (size_t)((g * 96 + i) * 96) * 128;
    for (int j = 0; j < 96; j++) {
        float a = 0.0f;
#pragma unroll
        for (int q = 0; q < 32; q++) a += l2s[j][q] * w1cs[q * 128 + tid];
        Cout[j * 128 + tid] = a;
    }
}

// ---------------------------------------------------------------------------
// Kernel 4 (dominant): per (g,t,i) compute logits[j].
//   h[j,k]   = relu(A[i,k] + B[j,k] + C[i,j,k] + b1[k])        (96 x 128)
//   y2[j,n]  = relu(h @ W2 + b2); logit[j] = y2 @ W3 + b3 (+mask)
//
// 64 threads: tx = tid&7 owns 8 contiguous n (4 f32x2); ty = tid>>3 owns 12 j.
// 48 FFMA2 per (thread,k). W2 read by LDG.128 (L1-resident, cheaper
// wavefronts than LDS.128, frees 32KB smem). hv via 3 LDS.128 per (thread,k).
// ---------------------------------------------------------------------------
__global__ void __launch_bounds__(64, 7) k_logits(const float* __restrict__ edge_w,
                                                  const float* __restrict__ udb1,
                                                  const float* __restrict__ udW2,
                                                  const float* __restrict__ udb2,
                                                  const float* __restrict__ udW3,
                                                  const float* __restrict__ udb3,
                                                  float* __restrict__ out) {
    int bid = blockIdx.x;                 // g*32*96 + t*96 + i
    int g = bid / (32 * 96);
    int rem = bid % (32 * 96);
    int t = rem / 96;
    int i = rem % 96;
    int tid = threadIdx.x;
    int tx = tid & 7;
    int ty = tid >> 3;                    // 0..7

    __shared__ __align__(16) float sh[96 * 36];     // h tile [j][k0..k0+31 +pad]
    __shared__ __align__(16) float sA[128];
    __shared__ float sW3[64];
    __shared__ float sb2[64];
    __shared__ float ews[96];

    // prologue loads (64 threads)
    {
        float a0 = g_A[bid * 128 + tid] + udb1[tid];
        float a1 = g_A[bid * 128 + 64 + tid] + udb1[64 + tid];
        sA[tid] = a0;
        sA[64 + tid] = a1;
        sW3[tid] = udW3[tid];
        sb2[tid] = udb2[tid];
        const float* ewrow = edge_w + (size_t)(96 * g + i) * 192 + 96 * g;
        ews[tid] = ewrow[tid];
        if (tid < 32) ews[64 + tid] = ewrow[64 + tid];
    }

    const float* Bb = g_B + (size_t)((g * 32 + t) * 96) * 128;
    const float* Cb = g_C + (size_t)((g * 96 + i) * 96) * 128;

    unsigned long long acc[12][4];
#pragma unroll
    for (int jj = 0; jj < 12; jj++)
#pragma unroll
        for (int p = 0; p < 4; p++) acc[jj][p] = 0ULL;

    const float4* sh4 = reinterpret_cast<const float4*>(sh);

    for (int kt = 0; kt < 4; kt++) {
        __syncthreads();  // guards sh reuse (and prologue smem on kt==0)
        // Build h tile: 96 j x 32 k = 768 float4 chunks, 12 per thread
#pragma unroll
        for (int it = 0; it < 12; it++) {
            int e = tid + it * 64;
            int j = e >> 3, kq = e & 7;
            int k0 = kt * 32 + kq * 4;
            float4 b4 = *reinterpret_cast<const float4*>(Bb + j * 128 + k0);
            float4 c4 = *reinterpret_cast<const float4*>(Cb + j * 128 + k0);
            float4 a4 = *reinterpret_cast<const float4*>(sA + k0);
            float4 v;
            v.x = fmaxf(a4.x + b4.x + c4.x, 0.0f);
            v.y = fmaxf(a4.y + b4.y + c4.y, 0.0f);
            v.z = fmaxf(a4.z + b4.z + c4.z, 0.0f);
            v.w = fmaxf(a4.w + b4.w + c4.w, 0.0f);
            *reinterpret_cast<float4*>(sh + j * 36 + kq * 4) = v;
        }
        __syncthreads();

#pragma unroll
        for (int k4 = 0; k4 < 8; k4++) {
            float hv[12][4];
#pragma unroll
            for (int jj = 0; jj < 12; jj++)
                *reinterpret_cast<float4*>(hv[jj]) = sh4[(ty * 12 + jj) * 9 + k4];
#pragma unroll
            for (int kk = 0; kk < 4; kk++) {
                const float* wrow = udW2 + (kt * 32 + k4 * 4 + kk) * 64 + tx * 8;
                ulonglong2 wa = __ldg(reinterpret_cast<const ulonglong2*>(wrow));
                ulonglong2 wb = __ldg(reinterpret_cast<const ulonglong2*>(wrow + 4));
#pragma unroll
                for (int jj = 0; jj < 12; jj++) {
                    unsigned long long hd = packdup(hv[jj][kk]);
                    ffma2(acc[jj][0], hd, wa.x);
                    ffma2(acc[jj][1], hd, wa.y);
                    ffma2(acc[jj][2], hd, wb.x);
                    ffma2(acc[jj][3], hd, wb.y);
                }
            }
        }
    }

    float b3 = udb3[0];
#pragma unroll
    for (int jj = 0; jj < 12; jj++) {
        float s = 0.0f;
#pragma unroll
        for (int p = 0; p < 4; p++) {
            int n = tx * 8 + p * 2;
            float f0, f1;
            unpack2(f0, f1, acc[jj][p]);
            s += fmaxf(f0 + sb2[n], 0.0f) * sW3[n];
            s += fmaxf(f1 + sb2[n + 1], 0.0f) * sW3[n + 1];
        }
#pragma unroll
        for (int off = 4; off; off >>= 1) s += __shfl_xor_sync(0xffffffffu, s, off);
        if (tx == 0) {
            int j = ty * 12 + jj;
            float L = s + b3;
            if (ews[j] == 0.0f && j != i) L = NEG_VAL;
            out[(size_t)bid * 96 + j] = L;
        }
    }
}

// ---------------------------------------------------------------------------
// Launch
// ---------------------------------------------------------------------------
extern "C" void kernel_launch(void* const* d_in, const int* in_sizes, int n_in,
                              void* d_out, int out_size) {
    int w0 = n_in - 20;
    const float* x      = (const float*)d_in[0];
    const float* edge_w = (const float*)d_in[1];
    const float* neW1 = (const float*)d_in[w0 + 0];
    const float* neb1 = (const float*)d_in[w0 + 1];
    const float* neW2 = (const float*)d_in[w0 + 2];
    const float* neb2 = (const float*)d_in[w0 + 3];
    const float* eeW1 = (const float*)d_in[w0 + 4];
    const float* eeb1 = (const float*)d_in[w0 + 5];
    const float* eeW2 = (const float*)d_in[w0 + 6];
    const float* eeb2 = (const float*)d_in[w0 + 7];
    const float* udW1 = (const float*)d_in[w0 + 8];
    const float* udb1 = (const float*)d_in[w0 + 9];
    const float* udW2 = (const float*)d_in[w0 + 10];
    const float* udb2 = (const float*)d_in[w0 + 11];
    const float* udW3 = (const float*)d_in[w0 + 12];
    const float* udb3 = (const float*)d_in[w0 + 13];
    const float* dpW1 = (const float*)d_in[w0 + 14];
    const float* dpb1 = (const float*)d_in[w0 + 15];
    const float* dpW2 = (const float*)d_in[w0 + 16];
    const float* dpb2 = (const float*)d_in[w0 + 17];
    const float* dpW3 = (const float*)d_in[w0 + 18];
    const float* dpb3 = (const float*)d_in[w0 + 19];

    float* out = (float*)d_out;
    const int CLASS_N = 2 * 32 * 96 * 96;  // 589824
    float* dist_out = out + CLASS_N;

    k_node_embed<<<6336 / EROWS, 128>>>(x, neW1, neb1, neW2, neb2);
    k_proj_dist<<<6144 / PROWS, 128>>>(udW1, dpW1, dpb1, dpW2, dpb2, dpW3, dpb3, dist_out);
    k_ee_c<<<2 * 96, 128>>>(edge_w, eeW1, eeb1, eeW2, eeb2, udW1);
    k_logits<<<2 * 32 * 96, 64>>>(edge_w, udb1, udW2, udb2, udW3, udb3, out);
}

// round 5
// speedup vs baseline: 4.7328x; 4.7328x over previous
#include <cuda_runtime.h>
#include <cuda_bf16.h>
#include <cstdint>

// Problem constants (hardcoded from reference):
//   PROJ=128, H=128, G=2, D=96, T=33, NEG=-1e9

#define NEG_VAL (-1000000000.0f)

// Scratch (device globals -- no allocations allowed)
__device__ float g_E[2 * 33 * 96 * 128];   // node embeddings
__device__ float g_A[2 * 32 * 96 * 128];   // xne @ udW1[0:128]
__device__ float g_B[2 * 32 * 96 * 128];   // xce @ udW1[128:256]
__device__ float g_C[2 * 96 * 96 * 128];   // ee  @ udW1[256:288]

// ---- tf32 helpers -----------------------------------------------------------
__device__ __forceinline__ uint32_t tf32r(float x) {
    uint32_t r;
    asm("cvt.rna.tf32.f32 %0, %1;" : "=r"(r) : "f"(x));
    return r;
}
__device__ __forceinline__ void mma_tf32(float c[4], uint32_t a0, uint32_t a1,
                                         uint32_t a2, uint32_t a3,
                                         uint32_t b0, uint32_t b1) {
    asm("mma.sync.aligned.m16n8k8.row.col.f32.tf32.tf32.f32 "
        "{%0,%1,%2,%3},{%4,%5,%6,%7},{%8,%9},{%0,%1,%2,%3};"
        : "+f"(c[0]), "+f"(c[1]), "+f"(c[2]), "+f"(c[3])
        : "r"(a0), "r"(a1), "r"(a2), "r"(a3), "r"(b0), "r"(b1));
}

// ---------------------------------------------------------------------------
// Kernel 1: node embeddings  E = relu(relu(x @ neW1 + b1) @ neW2 + b2)
// ---------------------------------------------------------------------------
#define EROWS 8
__global__ void k_node_embed(const float* __restrict__ x,
                             const float* __restrict__ W1, const float* __restrict__ b1,
                             const float* __restrict__ W2, const float* __restrict__ b2) {
    int r0 = blockIdx.x * EROWS;
    int tid = threadIdx.x;  // 128
    __shared__ float xv[EROWS][129];
    __shared__ float y1[EROWS][128];

    int g = r0 / (33 * 96);
    int rem = r0 % (33 * 96);
    int t = rem / 96;
    int i0 = rem % 96;
    const float* xb = x + (size_t)(g * 33 + t) * 128 * 192 + 96 * g + i0;

#pragma unroll
    for (int it = 0; it < 8; it++) {
        int e = tid + it * 128;
        int h = e >> 3;
        int ii = e & 7;
        xv[ii][h] = xb[h * 192 + ii];
    }
    __syncthreads();

    float acc[EROWS];
#pragma unroll
    for (int r = 0; r < EROWS; r++) acc[r] = b1[tid];
    for (int k = 0; k < 128; k++) {
        float w = W1[k * 128 + tid];
#pragma unroll
        for (int r = 0; r < EROWS; r++) acc[r] += xv[r][k] * w;
    }
#pragma unroll
    for (int r = 0; r < EROWS; r++) y1[r][tid] = fmaxf(acc[r], 0.0f);
    __syncthreads();

#pragma unroll
    for (int r = 0; r < EROWS; r++) acc[r] = b2[tid];
    for (int k = 0; k < 128; k++) {
        float w = W2[k * 128 + tid];
#pragma unroll
        for (int r = 0; r < EROWS; r++) acc[r] += y1[r][k] * w;
    }
#pragma unroll
    for (int r = 0; r < EROWS; r++) g_E[(r0 + r) * 128 + tid] = fmaxf(acc[r], 0.0f);
}

// ---------------------------------------------------------------------------
// Kernel 2: A/B projections + dist head.
// ---------------------------------------------------------------------------
#define PROWS 8
__global__ void k_proj_dist(const float* __restrict__ udW1,
                            const float* __restrict__ dpW1, const float* __restrict__ dpb1,
                            const float* __restrict__ dpW2, const float* __restrict__ dpb2,
                            const float* __restrict__ dpW3, const float* __restrict__ dpb3,
                            float* __restrict__ dist_out) {
    int r0 = blockIdx.x * PROWS;
    int tid = threadIdx.x;  // 128
    int g = r0 / (32 * 96);
    int rem = r0 % (32 * 96);
    int t = rem / 96;
    int i0 = rem % 96;

    __shared__ float Ec[PROWS][128];
    __shared__ float En[PROWS][128];
    __shared__ float y1d[PROWS][128];

    for (int e = tid; e < PROWS * 128; e += 128) {
        int r = e >> 7, k = e & 127;
        Ec[r][k] = g_E[((g * 33 + t) * 96 + i0 + r) * 128 + k];
        En[r][k] = g_E[((g * 33 + t + 1) * 96 + i0 + r) * 128 + k];
    }
    __syncthreads();

    float accA[PROWS], accB[PROWS], accD[PROWS];
#pragma unroll
    for (int r = 0; r < PROWS; r++) { accA[r] = 0.0f; accB[r] = 0.0f; accD[r] = 0.0f; }

    for (int k = 0; k < 128; k++) {
        float wa = udW1[k * 128 + tid];
        float wb = udW1[(128 + k) * 128 + tid];
        float wc = dpW1[k * 128 + tid];
        float wd = dpW1[(128 + k) * 128 + tid];
#pragma unroll
        for (int r = 0; r < PROWS; r++) {
            accA[r] += En[r][k] * wa;
            accB[r] += Ec[r][k] * wb;
            accD[r] += Ec[r][k] * wc + En[r][k] * wd;
        }
    }
    float db1 = dpb1[tid];
#pragma unroll
    for (int r = 0; r < PROWS; r++) {
        g_A[(r0 + r) * 128 + tid] = accA[r];
        g_B[(r0 + r) * 128 + tid] = accB[r];
        y1d[r][tid] = fmaxf(accD[r] + db1, 0.0f);
    }
    __syncthreads();

    int r = tid >> 4;
    int q = tid & 15;
    float s = 0.0f;
#pragma unroll
    for (int nn = 0; nn < 4; nn++) {
        int n = q * 4 + nn;
        float a = dpb2[n];
        for (int k = 0; k < 128; k++) a += y1d[r][k] * dpW2[k * 64 + n];
        s += fmaxf(a, 0.0f) * dpW3[n];
    }
#pragma unroll
    for (int off = 8; off; off >>= 1) s += __shfl_xor_sync(0xffffffffu, s, off);
    if (q == 0) dist_out[r0 + r] = s + dpb3[0];
}

// ---------------------------------------------------------------------------
// Kernel 3: edge MLP + C projection.
// ---------------------------------------------------------------------------
__global__ void k_ee_c(const float* __restrict__ edge_w,
                       const float* __restrict__ eeW1, const float* __restrict__ eeb1,
                       const float* __restrict__ eeW2, const float* __restrict__ eeb2,
                       const float* __restrict__ udW1) {
    int g = blockIdx.x / 96;
    int i = blockIdx.x % 96;
    int tid = threadIdx.x;  // 128

    __shared__ float l2s[96][33];
    __shared__ float w1s[32], b1s[32], b2s[32];
    __shared__ float w2s[32 * 32];
    __shared__ float w1cs[32 * 128];
    __shared__ float ews[96];

    if (tid < 32) { w1s[tid] = eeW1[tid]; b1s[tid] = eeb1[tid]; b2s[tid] = eeb2[tid]; }
    for (int e = tid; e < 1024; e += 128) w2s[e] = eeW2[e];
    for (int e = tid; e < 4096; e += 128) w1cs[e] = udW1[256 * 128 + e];
    if (tid < 96) ews[tid] = edge_w[(96 * g + i) * 192 + 96 * g + tid];
    __syncthreads();

    for (int e = tid; e < 96 * 32; e += 128) {
        int j = e >> 5, q = e & 31;
        float e0 = ews[j];
        float a = b2s[q];
#pragma unroll
        for (int p = 0; p < 32; p++) {
            float l1 = fmaxf(e0 * w1s[p] + b1s[p], 0.0f);
            a += l1 * w2s[p * 32 + q];
        }
        l2s[j][q] = fmaxf(a, 0.0f);
    }
    __syncthreads();

    float* Cout = g_C + (size_t)((g * 96 + i) * 96) * 128;
    for (int j = 0; j < 96; j++) {
        float a = 0.0f;
#pragma unroll
        for (int q = 0; q < 32; q++) a += l2s[j][q] * w1cs[q * 128 + tid];
        Cout[j * 128 + tid] = a;
    }
}

// ---------------------------------------------------------------------------
// Kernel 4 (dominant): per (g,t,i) logits via tf32 tensor-core mma.sync.
//   h[j,k]   = relu(A[i,k] + B[j,k] + C[i,j,k] + b1[k])        (96 x 128)
//   y2[j,n]  = relu(h @ W2 + b2); logit[j] = y2 @ W3 + b3 (+mask)
//
// 96 threads = 3 warps. Warp w owns rows [32w, 32w+32) = 2 m16-tiles,
// all 8 n8-tiles, K=128 as 16 k8 steps (m16n8k8 tf32 HMMA).
// W2 staged to smem with XOR-8 swizzle (32KB exactly, conflict-free B frags).
// h built per 32-k chunk into stride-36 tile (conflict-free A frags).
// tf32 only on the 128-deep dot; everything else fp32-exact.
// ---------------------------------------------------------------------------
__global__ void __launch_bounds__(96) k_logits(const float* __restrict__ edge_w,
                                               const float* __restrict__ udb1,
                                               const float* __restrict__ udW2,
                                               const float* __restrict__ udb2,
                                               const float* __restrict__ udW3,
                                               const float* __restrict__ udb3,
                                               float* __restrict__ out) {
    int bid = blockIdx.x;                 // g*32*96 + t*96 + i
    int g = bid / (32 * 96);
    int rem = bid % (32 * 96);
    int t = rem / 96;
    int i = rem % 96;
    int tid = threadIdx.x;
    int l = tid & 31;                     // lane
    int w = tid >> 5;                     // warp 0..2
    int tg = l & 3;                       // threadID_in_group
    int gp = l >> 2;                      // groupID 0..7

    __shared__ __align__(16) float sW2[128 * 64];   // 32 KB, xor-swizzled rows
    __shared__ __align__(16) float sh[96 * 36];     // h chunk [j][kc], stride 36
    __shared__ __align__(16) float sA[128];
    __shared__ float sW3[64];
    __shared__ float sb2[64];
    __shared__ float ews[96];

    // Stage W2 (tf32-rounded) with per-row XOR-8 swizzle: phys n = n ^ (8*(k&3))
    for (int e = tid; e < 2048; e += 96) {
        int k = e >> 4, nq = e & 15;
        float4 v = reinterpret_cast<const float4*>(udW2)[e];
        v.x = __uint_as_float(tf32r(v.x));
        v.y = __uint_as_float(tf32r(v.y));
        v.z = __uint_as_float(tf32r(v.z));
        v.w = __uint_as_float(tf32r(v.w));
        int n0 = (nq * 4) ^ (8 * (k & 3));
        *reinterpret_cast<float4*>(sW2 + k * 64 + n0) = v;
    }
    for (int e = tid; e < 128; e += 96) sA[e] = g_A[bid * 128 + e] + udb1[e];
    if (tid < 64) { sW3[tid] = udW3[tid]; sb2[tid] = udb2[tid]; }
    ews[tid] = edge_w[(size_t)(96 * g + i) * 192 + 96 * g + tid];

    const float* Bb = g_B + (size_t)((g * 32 + t) * 96) * 128;
    const float* Cb = g_C + (size_t)((g * 96 + i) * 96) * 128;

    float acc[2][8][4];
#pragma unroll
    for (int mt = 0; mt < 2; mt++)
#pragma unroll
        for (int nt = 0; nt < 8; nt++)
#pragma unroll
            for (int p = 0; p < 4; p++) acc[mt][nt][p] = 0.0f;

    for (int kt = 0; kt < 4; kt++) {
        __syncthreads();  // guards sh reuse (and prologue smem on kt==0)
        // Build h chunk: 96 j x 32 k = 768 float4, 8 per thread, tf32-rounded
#pragma unroll
        for (int it = 0; it < 8; it++) {
            int e = tid + it * 96;
            int j = e >> 3, kq = e & 7;
            int k0 = kt * 32 + kq * 4;
            float4 b4 = *reinterpret_cast<const float4*>(Bb + j * 128 + k0);
            float4 c4 = *reinterpret_cast<const float4*>(Cb + j * 128 + k0);
            float4 a4 = *reinterpret_cast<const float4*>(sA + k0);
            float4 v;
            v.x = __uint_as_float(tf32r(fmaxf(a4.x + b4.x + c4.x, 0.0f)));
            v.y = __uint_as_float(tf32r(fmaxf(a4.y + b4.y + c4.y, 0.0f)));
            v.z = __uint_as_float(tf32r(fmaxf(a4.z + b4.z + c4.z, 0.0f)));
            v.w = __uint_as_float(tf32r(fmaxf(a4.w + b4.w + c4.w, 0.0f)));
            *reinterpret_cast<float4*>(sh + j * 36 + kq * 4) = v;
        }
        __syncthreads();

#pragma unroll
        for (int k8 = 0; k8 < 4; k8++) {
            int kc = k8 * 8;
            uint32_t a[2][4];
#pragma unroll
            for (int mt = 0; mt < 2; mt++) {
                int jb = w * 32 + mt * 16;
                a[mt][0] = __float_as_uint(sh[(jb + gp) * 36 + kc + tg]);
                a[mt][1] = __float_as_uint(sh[(jb + 8 + gp) * 36 + kc + tg]);
                a[mt][2] = __float_as_uint(sh[(jb + gp) * 36 + kc + tg + 4]);
                a[mt][3] = __float_as_uint(sh[(jb + 8 + gp) * 36 + kc + tg + 4]);
            }
            int Kg = kt * 32 + kc + tg;       // global k for b0 (b1: +4)
            int nx = 8 * tg;                  // row xor
#pragma unroll
            for (int nt = 0; nt < 8; nt++) {
                int ncol = (nt * 8 + gp) ^ nx;
                uint32_t b0 = __float_as_uint(sW2[Kg * 64 + ncol]);
                uint32_t b1 = __float_as_uint(sW2[(Kg + 4) * 64 + ncol]);
                mma_tf32(acc[0][nt], a[0][0], a[0][1], a[0][2], a[0][3], b0, b1);
                mma_tf32(acc[1][nt], a[1][0], a[1][1], a[1][2], a[1][3], b0, b1);
            }
        }
    }

    // Epilogue: relu + W3 dot + lane-group reduce + mask + store
    float b3 = udb3[0];
#pragma unroll
    for (int mt = 0; mt < 2; mt++) {
        float s0 = 0.0f, s1 = 0.0f;
#pragma unroll
        for (int nt = 0; nt < 8; nt++) {
            int n = nt * 8 + tg * 2;
            s0 += fmaxf(acc[mt][nt][0] + sb2[n], 0.0f) * sW3[n]
                + fmaxf(acc[mt][nt][1] + sb2[n + 1], 0.0f) * sW3[n + 1];
            s1 += fmaxf(acc[mt][nt][2] + sb2[n], 0.0f) * sW3[n]
                + fmaxf(acc[mt][nt][3] + sb2[n + 1], 0.0f) * sW3[n + 1];
        }
        s0 += __shfl_xor_sync(0xffffffffu, s0, 1);
        s0 += __shfl_xor_sync(0xffffffffu, s0, 2);
        s1 += __shfl_xor_sync(0xffffffffu, s1, 1);
        s1 += __shfl_xor_sync(0xffffffffu, s1, 2);
        if (tg == 0) {
            int j0 = w * 32 + mt * 16 + gp;
            float L0 = s0 + b3;
            float L1 = s1 + b3;
            if (ews[j0] == 0.0f && j0 != i) L0 = NEG_VAL;
            if (ews[j0 + 8] == 0.0f && (j0 + 8) != i) L1 = NEG_VAL;
            out[(size_t)bid * 96 + j0] = L0;
            out[(size_t)bid * 96 + j0 + 8] = L1;
        }
    }
}

// ---------------------------------------------------------------------------
// Launch
// ---------------------------------------------------------------------------
extern "C" void kernel_launch(void* const* d_in, const int* in_sizes, int n_in,
                              void* d_out, int out_size) {
    int w0 = n_in - 20;
    const float* x      = (const float*)d_in[0];
    const float* edge_w = (const float*)d_in[1];
    const float* neW1 = (const float*)d_in[w0 + 0];
    const float* neb1 = (const float*)d_in[w0 + 1];
    const float* neW2 = (const float*)d_in[w0 + 2];
    const float* neb2 = (const float*)d_in[w0 + 3];
    const float* eeW1 = (const float*)d_in[w0 + 4];
    const float* eeb1 = (const float*)d_in[w0 + 5];
    const float* eeW2 = (const float*)d_in[w0 + 6];
    const float* eeb2 = (const float*)d_in[w0 + 7];
    const float* udW1 = (const float*)d_in[w0 + 8];
    const float* udb1 = (const float*)d_in[w0 + 9];
    const float* udW2 = (const float*)d_in[w0 + 10];
    const float* udb2 = (const float*)d_in[w0 + 11];
    const float* udW3 = (const float*)d_in[w0 + 12];
    const float* udb3 = (const float*)d_in[w0 + 13];
    const float* dpW1 = (const float*)d_in[w0 + 14];
    const float* dpb1 = (const float*)d_in[w0 + 15];
    const float* dpW2 = (const float*)d_in[w0 + 16];
    const float* dpb2 = (const float*)d_in[w0 + 17];
    const float* dpW3 = (const float*)d_in[w0 + 18];
    const float* dpb3 = (const float*)d_in[w0 + 19];

    float* out = (float*)d_out;
    const int CLASS_N = 2 * 32 * 96 * 96;  // 589824
    float* dist_out = out + CLASS_N;

    k_node_embed<<<6336 / EROWS, 128>>>(x, neW1, neb1, neW2, neb2);
    k_proj_dist<<<6144 / PROWS, 128>>>(udW1, dpW1, dpb1, dpW2, dpb2, dpW3, dpb3, dist_out);
    k_ee_c<<<2 * 96, 128>>>(edge_w, eeW1, eeb1, eeW2, eeb2, udW1);
    k_logits<<<2 * 32 * 96, 96>>>(edge_w, udb1, udW2, udb2, udW3, udb3, out);
}